// round 9
// baseline (speedup 1.0000x reference)
#include <cuda_runtime.h>
#include <cstdint>

#define NNODES 10000
#define NEDGES 100000
#define ET     (NEDGES + NNODES)
#define KDIM   1024
#define HEADS  3
#define CH     1024
#define HC     3072   // HEADS*CH
#define HC2    6144   // 2*HC
#define NCLS   460
#define NEG    0.2f
#define SMAX   1024

// ---------------- device scratch (no allocation allowed) ----------------
__device__ float g_xlr[(size_t)NNODES * HC2];   // [N, xl(3072) | xr(3072)]
__device__ float g_hpre[(size_t)NNODES * KDIM]; // aggregated (+bias, /H), tf32-rounded
__device__ float g_xc[(size_t)NNODES * KDIM];   // tf32(x)
__device__ float g_wc[(size_t)KDIM * HC2];      // tf32([Wl|Wr]) merged, row-major [K,6144]
__device__ float g_wfc[(size_t)KDIM * NCLS];    // tf32(Wfc)
__device__ int   g_deg[NNODES];
__device__ int   g_off[NNODES + 1];
__device__ int   g_cur[NNODES];
__device__ int   g_csrc[ET];
__device__ int   g_is64;

// ---------------- helpers ----------------
__device__ __forceinline__ float ftf32(float x) {
    float r;
    asm("cvt.rna.tf32.f32 %0, %1;" : "=f"(r) : "f"(x));
    return r;
}

__device__ __forceinline__ void cpa16(uint32_t dst, const float* src, bool p) {
    asm volatile("cp.async.cg.shared.global [%0], [%1], 16, %2;\n"
                 :: "r"(dst), "l"(src), "r"(p ? 16 : 0));
}

// ---------------- edge_index dtype detection (parallel) ----------------
// JAX without x64 silently stores int64-annotated arrays as int32. Interpret
// the first 1000 words as int64: genuine int64 node ids are all in [0, N);
// int32 data packed two-per-word lands out of range almost surely.
__global__ void k_detect(const long long* __restrict__ ei64) {
    __shared__ int bad;
    if (threadIdx.x == 0) bad = 0;
    __syncthreads();
    for (int i = threadIdx.x; i < 1000; i += 256) {
        long long v = ei64[i];
        if (v < 0 || v >= NNODES) bad = 1;  // benign race
    }
    __syncthreads();
    if (threadIdx.x == 0) g_is64 = bad ? 0 : 1;
}

__device__ __forceinline__ int clampN(int v) {
    return v < 0 ? 0 : (v >= NNODES ? NNODES - 1 : v);
}

// ---------------- CSR build (by destination) ----------------
__global__ void k_zero() {
    int i = blockIdx.x * blockDim.x + threadIdx.x;
    if (i < NNODES) g_deg[i] = 0;
}

__global__ void k_deg(const long long* __restrict__ e64,
                      const int* __restrict__ e32) {
    int i = blockIdx.x * blockDim.x + threadIdx.x;
    if (i >= ET) return;
    int dst;
    if (i < NEDGES) dst = clampN(g_is64 ? (int)e64[2 * i + 1] : e32[2 * i + 1]);
    else            dst = i - NEDGES;
    atomicAdd(&g_deg[dst], 1);
}

// coarsened single-pass scan: 1024 threads x 10 elements
__global__ void k_scan() {
    __shared__ int wt[32];
    const int tid = threadIdx.x, lane = tid & 31, warp = tid >> 5;
    const int PER = 10;
    int base = tid * PER;
    int v[PER];
    int run = 0;
#pragma unroll
    for (int t = 0; t < PER; t++) {
        int idx = base + t;
        int d = (idx < NNODES) ? g_deg[idx] : 0;
        run += d; v[t] = run;
    }
    int ws = run;
#pragma unroll
    for (int o = 1; o < 32; o <<= 1) {
        int t = __shfl_up_sync(0xffffffffu, ws, o);
        if (lane >= o) ws += t;
    }
    if (lane == 31) wt[warp] = ws;
    __syncthreads();
    if (warp == 0) {
        int t = wt[lane];
#pragma unroll
        for (int o = 1; o < 32; o <<= 1) {
            int u = __shfl_up_sync(0xffffffffu, t, o);
            if (lane >= o) t += u;
        }
        wt[lane] = t;
    }
    __syncthreads();
    int off = (warp ? wt[warp - 1] : 0) + (ws - run);
#pragma unroll
    for (int t = 0; t < PER; t++) {
        int idx = base + t;
        if (idx < NNODES) {
            int d = v[t] - (t ? v[t - 1] : 0);
            g_off[idx + 1] = off + v[t];
            g_cur[idx]     = off + v[t] - d;
        }
    }
    if (tid == 0) g_off[0] = 0;
}

__global__ void k_fill(const long long* __restrict__ e64,
                       const int* __restrict__ e32) {
    int i = blockIdx.x * blockDim.x + threadIdx.x;
    if (i >= ET) return;
    int src, dst;
    if (i < NEDGES) {
        if (g_is64) { src = (int)e64[2 * i]; dst = (int)e64[2 * i + 1]; }
        else        { src = e32[2 * i];      dst = e32[2 * i + 1]; }
        src = clampN(src); dst = clampN(dst);
    } else {
        src = i - NEDGES; dst = src;
    }
    int pos = atomicAdd(&g_cur[dst], 1);
    if (pos >= 0 && pos < ET) g_csrc[pos] = src;
}

// ---------------- pre-convert operands to tf32 (rna) ----------------
__global__ void k_cvtX(const float* __restrict__ x) {
    int i = blockIdx.x * blockDim.x + threadIdx.x;
    if (i >= NNODES * KDIM / 4) return;
    float4 v = ((const float4*)x)[i];
    v.x = ftf32(v.x); v.y = ftf32(v.y); v.z = ftf32(v.z); v.w = ftf32(v.w);
    ((float4*)g_xc)[i] = v;
}

__global__ void k_cvtW(const float* __restrict__ Wl, const float* __restrict__ Wr) {
    int i = blockIdx.x * blockDim.x + threadIdx.x;
    if (i >= KDIM * HC2 / 4) return;
    int k  = i / (HC2 / 4);
    int c4 = i - k * (HC2 / 4);
    float4 v = (c4 < HC / 4)
        ? ((const float4*)Wl)[(size_t)k * (HC / 4) + c4]
        : ((const float4*)Wr)[(size_t)k * (HC / 4) + (c4 - HC / 4)];
    v.x = ftf32(v.x); v.y = ftf32(v.y); v.z = ftf32(v.z); v.w = ftf32(v.w);
    ((float4*)g_wc)[i] = v;
}

__global__ void k_cvtF(const float* __restrict__ Wfc) {
    int i = blockIdx.x * blockDim.x + threadIdx.x;
    if (i >= KDIM * NCLS / 4) return;
    float4 v = ((const float4*)Wfc)[i];
    v.x = ftf32(v.x); v.y = ftf32(v.y); v.z = ftf32(v.z); v.w = ftf32(v.w);
    ((float4*)g_wfc)[i] = v;
}

// ---------------- cp.async double-buffered tf32 GEMM, 256x128 tiles ----------------
// mode 0: C[g_xlr] = g_xc[M,K] @ g_wc[K,6144] + (bl|br)
// mode 1: Cout     = g_hpre[M,K] @ g_wfc[K,460] + bfc
// SMEM: As 2 x 8192 floats (256x32), Bs 2 x 4096 floats (32x128) = 96 KB
__global__ __launch_bounds__(256, 1) void k_gemm(
    int mode, int M, int Ntot, int nsplit,
    const float* __restrict__ bias1, const float* __restrict__ bias2,
    float* __restrict__ Cout)
{
    extern __shared__ float smem[];

    const float* Ap = mode ? g_hpre : g_xc;
    const float* Bp = mode ? g_wfc : g_wc;
    float* Cp = mode ? Cout : g_xlr;
    const int K = KDIM, ldb = Ntot, ldc = Ntot;

    const int tid  = threadIdx.x;
    const int lane = tid & 31, warp = tid >> 5;
    const int wm = warp >> 1, wn = warp & 1;       // 4 x 2 warp grid, 64x64 per warp
    const int g  = lane >> 2, tg = lane & 3;
    const int m0 = blockIdx.y * 256, n0 = blockIdx.x * 128;

    const int ar  = tid >> 3;        // A row 0..31 (+i*32, 8 iters)
    const int akc = (tid & 7) * 4;   // A k-chunk
    const int bkr = tid >> 5;        // B k row 0..7 (+i*8, 4 iters)
    const int bnc = (tid & 31) * 4;  // B n-chunk

    const uint32_t sb = (uint32_t)__cvta_generic_to_shared(smem);

#define ISSUE(k0, st) do {                                                      \
    _Pragma("unroll")                                                           \
    for (int i = 0; i < 8; i++) {                                               \
        int r = ar + i * 32; int gm = m0 + r;                                   \
        const float* src = Ap + (size_t)(gm < M ? gm : 0) * K + (k0) + akc;     \
        uint32_t d = sb + (((st) * 8192 + r * 32 + (akc ^ ((r & 7) << 2))) << 2); \
        cpa16(d, src, gm < M);                                                  \
    }                                                                           \
    _Pragma("unroll")                                                           \
    for (int i = 0; i < 4; i++) {                                               \
        int kr = bkr + i * 8; int gn = n0 + bnc; bool ok = gn < Ntot;           \
        const float* src = Bp + (size_t)((k0) + kr) * ldb + (ok ? gn : 0);      \
        uint32_t d = sb + ((16384 + (st) * 4096 + kr * 128 + (bnc ^ ((kr & 3) << 3))) << 2); \
        cpa16(d, src, ok);                                                      \
    }                                                                           \
} while (0)

    float acc[4][8][4];
#pragma unroll
    for (int a = 0; a < 4; a++)
#pragma unroll
        for (int b = 0; b < 8; b++)
#pragma unroll
            for (int c = 0; c < 4; c++) acc[a][b][c] = 0.f;

    ISSUE(0, 0);
    asm volatile("cp.async.commit_group;\n");

    const int niter = K / 32;
    for (int it = 0; it < niter; it++) {
        if (it + 1 < niter) {
            ISSUE((it + 1) * 32, (it + 1) & 1);
            asm volatile("cp.async.commit_group;\n");
            asm volatile("cp.async.wait_group 1;\n");
        } else {
            asm volatile("cp.async.wait_group 0;\n");
        }
        __syncthreads();

        const float* A0 = smem + (it & 1) * 8192;
        const float* B0 = smem + 16384 + (it & 1) * 4096;
#pragma unroll
        for (int kk = 0; kk < 4; kk++) {
            const int kb = kk * 8;
            const int k1 = kb + tg, k2 = k1 + 4;
            uint32_t af[4][4];
            uint32_t bf[8][2];
#pragma unroll
            for (int mi = 0; mi < 4; mi++) {
                int r0 = wm * 64 + mi * 16 + g;
                int r1 = r0 + 8;
                af[mi][0] = __float_as_uint(A0[r0 * 32 + (k1 ^ ((r0 & 7) << 2))]);
                af[mi][1] = __float_as_uint(A0[r1 * 32 + (k1 ^ ((r1 & 7) << 2))]);
                af[mi][2] = __float_as_uint(A0[r0 * 32 + (k2 ^ ((r0 & 7) << 2))]);
                af[mi][3] = __float_as_uint(A0[r1 * 32 + (k2 ^ ((r1 & 7) << 2))]);
            }
#pragma unroll
            for (int ni = 0; ni < 8; ni++) {
                int n = wn * 64 + ni * 8 + g;
                bf[ni][0] = __float_as_uint(B0[k1 * 128 + (n ^ ((k1 & 3) << 3))]);
                bf[ni][1] = __float_as_uint(B0[k2 * 128 + (n ^ ((k2 & 3) << 3))]);
            }
#pragma unroll
            for (int mi = 0; mi < 4; mi++)
#pragma unroll
                for (int ni = 0; ni < 8; ni++)
                    asm volatile(
                        "mma.sync.aligned.m16n8k8.row.col.f32.tf32.tf32.f32 "
                        "{%0,%1,%2,%3}, {%4,%5,%6,%7}, {%8,%9}, {%0,%1,%2,%3};\n"
                        : "+f"(acc[mi][ni][0]), "+f"(acc[mi][ni][1]),
                          "+f"(acc[mi][ni][2]), "+f"(acc[mi][ni][3])
                        : "r"(af[mi][0]), "r"(af[mi][1]), "r"(af[mi][2]), "r"(af[mi][3]),
                          "r"(bf[ni][0]), "r"(bf[ni][1]));
        }
        __syncthreads();
    }
#undef ISSUE

    // epilogue: c0 (g, 2tg), c1 (g, 2tg+1), c2/c3 at row+8
#pragma unroll
    for (int mi = 0; mi < 4; mi++) {
        int row0 = m0 + wm * 64 + mi * 16 + g;
#pragma unroll
        for (int ni = 0; ni < 8; ni++) {
            int col = n0 + wn * 64 + ni * 8 + tg * 2;
            if (col < Ntot) {
                float b0, b1;
                if (col < nsplit) { b0 = bias1[col]; b1 = bias1[col + 1]; }
                else              { b0 = bias2[col - nsplit]; b1 = bias2[col - nsplit + 1]; }
                if (row0 < M) {
                    float2 o = make_float2(acc[mi][ni][0] + b0, acc[mi][ni][1] + b1);
                    *(float2*)(Cp + (size_t)row0 * ldc + col) = o;
                }
                int row1 = row0 + 8;
                if (row1 < M) {
                    float2 o = make_float2(acc[mi][ni][2] + b0, acc[mi][ni][3] + b1);
                    *(float2*)(Cp + (size_t)row1 * ldc + col) = o;
                }
            }
        }
    }
}

// ---------------- fused online-softmax node kernel ----------------
// One block per node; each xl[j] row read exactly once; 1 barrier per edge
// (parity double-buffered warp partials).
__global__ __launch_bounds__(256) void k_node(const float* __restrict__ att,
                                              const float* __restrict__ bias)
{
    __shared__ int   ssrc[SMAX];
    __shared__ float wred[2][24];

    const int n    = blockIdx.x;
    const int tid  = threadIdx.x;
    const int lane = tid & 31, warp = tid >> 5;
    const int s    = g_off[n];
    const int deg  = g_off[n + 1] - s;
    const bool insm = (deg <= SMAX);

    // xr[n] and att live entirely in registers (each thread owns 4 ch/head)
    const float4* xr4 = (const float4*)(g_xlr + (size_t)n * HC2 + HC);
    float4 r0 = __ldg(xr4 + tid), r1 = __ldg(xr4 + tid + 256), r2 = __ldg(xr4 + tid + 512);
    const float4* at4 = (const float4*)att;
    float4 a0 = at4[tid], a1 = at4[tid + 256], a2 = at4[tid + 512];

    for (int i = tid; i < deg && i < SMAX; i += 256) ssrc[i] = g_csrc[s + i];
    __syncthreads();
    // deterministic order: sort srcs ascending (deg ~11)
    if (tid == 0 && insm && deg > 1) {
        for (int i = 1; i < deg; i++) {
            int v = ssrc[i]; int j = i - 1;
            while (j >= 0 && ssrc[j] > v) { ssrc[j + 1] = ssrc[j]; j--; }
            ssrc[j + 1] = v;
        }
    }
    __syncthreads();

    float m0 = -1e30f, m1 = -1e30f, m2 = -1e30f;
    float d0 = 0.f,   d1 = 0.f,   d2 = 0.f;
    float4 A0 = make_float4(0.f, 0.f, 0.f, 0.f);
    float4 A1 = A0, A2 = A0;

    // prefetch edge 0
    int j0 = insm ? ssrc[0] : g_csrc[s];
    const float4* p = (const float4*)(g_xlr + (size_t)j0 * HC2);
    float4 v0 = __ldg(p + tid), v1 = __ldg(p + tid + 256), v2 = __ldg(p + tid + 512);

    for (int i = 0; i < deg; i++) {
        float4 c0 = v0, c1 = v1, c2 = v2;
        if (i + 1 < deg) {
            int j2 = insm ? ssrc[i + 1] : g_csrc[s + i + 1];
            const float4* p2 = (const float4*)(g_xlr + (size_t)j2 * HC2);
            v0 = __ldg(p2 + tid); v1 = __ldg(p2 + tid + 256); v2 = __ldg(p2 + tid + 512);
        }
        // per-thread partial score per head
        float p0, p1, p2s, t;
        t = c0.x + r0.x; t = t > 0.f ? t : NEG * t; p0  = t * a0.x;
        t = c0.y + r0.y; t = t > 0.f ? t : NEG * t; p0 += t * a0.y;
        t = c0.z + r0.z; t = t > 0.f ? t : NEG * t; p0 += t * a0.z;
        t = c0.w + r0.w; t = t > 0.f ? t : NEG * t; p0 += t * a0.w;
        t = c1.x + r1.x; t = t > 0.f ? t : NEG * t; p1  = t * a1.x;
        t = c1.y + r1.y; t = t > 0.f ? t : NEG * t; p1 += t * a1.y;
        t = c1.z + r1.z; t = t > 0.f ? t : NEG * t; p1 += t * a1.z;
        t = c1.w + r1.w; t = t > 0.f ? t : NEG * t; p1 += t * a1.w;
        t = c2.x + r2.x; t = t > 0.f ? t : NEG * t; p2s  = t * a2.x;
        t = c2.y + r2.y; t = t > 0.f ? t : NEG * t; p2s += t * a2.y;
        t = c2.z + r2.z; t = t > 0.f ? t : NEG * t; p2s += t * a2.z;
        t = c2.w + r2.w; t = t > 0.f ? t : NEG * t; p2s += t * a2.w;
#pragma unroll
        for (int o = 16; o; o >>= 1) {
            p0  += __shfl_xor_sync(0xffffffffu, p0,  o);
            p1  += __shfl_xor_sync(0xffffffffu, p1,  o);
            p2s += __shfl_xor_sync(0xffffffffu, p2s, o);
        }
        float* wb = wred[i & 1];
        if (lane == 0) {
            wb[warp * 3]     = p0;
            wb[warp * 3 + 1] = p1;
            wb[warp * 3 + 2] = p2s;
        }
        __syncthreads();
        float s0 = 0.f, s1 = 0.f, s2 = 0.f;
#pragma unroll
        for (int w = 0; w < 8; w++) {
            s0 += wb[w * 3]; s1 += wb[w * 3 + 1]; s2 += wb[w * 3 + 2];
        }

        // online softmax update (redundant per thread, identical results)
        float mn, sc, e;
        mn = fmaxf(m0, s0); sc = __expf(m0 - mn); e = __expf(s0 - mn);
        d0 = d0 * sc + e; m0 = mn;
        A0.x = A0.x * sc + e * c0.x; A0.y = A0.y * sc + e * c0.y;
        A0.z = A0.z * sc + e * c0.z; A0.w = A0.w * sc + e * c0.w;
        mn = fmaxf(m1, s1); sc = __expf(m1 - mn); e = __expf(s1 - mn);
        d1 = d1 * sc + e; m1 = mn;
        A1.x = A1.x * sc + e * c1.x; A1.y = A1.y * sc + e * c1.y;
        A1.z = A1.z * sc + e * c1.z; A1.w = A1.w * sc + e * c1.w;
        mn = fmaxf(m2, s2); sc = __expf(m2 - mn); e = __expf(s2 - mn);
        d2 = d2 * sc + e; m2 = mn;
        A2.x = A2.x * sc + e * c2.x; A2.y = A2.y * sc + e * c2.y;
        A2.z = A2.z * sc + e * c2.z; A2.w = A2.w * sc + e * c2.w;
    }

    float i0 = 1.f / (d0 + 1e-16f);
    float i1 = 1.f / (d1 + 1e-16f);
    float i2 = 1.f / (d2 + 1e-16f);
    const float third = 1.f / 3.f;
    float4 bb = ((const float4*)bias)[tid];
    float4 o;
    o.x = ftf32((A0.x * i0 + A1.x * i1 + A2.x * i2) * third + bb.x);
    o.y = ftf32((A0.y * i0 + A1.y * i1 + A2.y * i2) * third + bb.y);
    o.z = ftf32((A0.z * i0 + A1.z * i1 + A2.z * i2) * third + bb.z);
    o.w = ftf32((A0.w * i0 + A1.w * i1 + A2.w * i2) * third + bb.w);
    ((float4*)(g_hpre + (size_t)n * KDIM))[tid] = o;
}

// ---------------- launch ----------------
extern "C" void kernel_launch(void* const* d_in, const int* in_sizes, int n_in,
                              void* d_out, int out_size) {
    (void)n_in;
    const float*     x      = (const float*)d_in[0];
    const long long* e64    = (const long long*)d_in[1];
    const int*       e32    = (const int*)d_in[1];
    const float*     Wl     = (const float*)d_in[2];
    const float*     bl     = (const float*)d_in[3];
    const float*     Wr     = (const float*)d_in[4];
    const float*     br     = (const float*)d_in[5];
    const float*     att    = (const float*)d_in[6];
    const float*     bias   = (const float*)d_in[7];
    const float*     Wfc    = (const float*)d_in[8];
    const float*     bfc    = (const float*)d_in[9];
    const float*     exps   = (const float*)d_in[10];
    const float*     exps_c = (const float*)d_in[11];
    float* out = (float*)d_out;

    cudaFuncSetAttribute(k_gemm, cudaFuncAttributeMaxDynamicSharedMemorySize, 98304);

    // detect int32 vs int64 edge_index, then CSR build (by destination)
    k_detect<<<1, 256>>>(e64);
    k_zero<<<(NNODES + 255) / 256, 256>>>();
    k_deg<<<(ET + 255) / 256, 256>>>(e64, e32);
    k_scan<<<1, 1024>>>();
    k_fill<<<(ET + 255) / 256, 256>>>(e64, e32);

    // pre-convert operands to tf32 (rna)
    k_cvtX<<<(NNODES * KDIM / 4 + 255) / 256, 256>>>(x);
    k_cvtW<<<(KDIM * HC2 / 4 + 255) / 256, 256>>>(Wl, Wr);
    k_cvtF<<<(KDIM * NCLS / 4 + 255) / 256, 256>>>(Wfc);

    // xl | xr = x @ [Wl | Wr] + [bl | br]   -> g_xlr
    {
        dim3 grid(HC2 / 128, (NNODES + 255) / 256);
        k_gemm<<<grid, 256, 98304>>>(0, NNODES, HC2, HC, bl, br, nullptr);
    }

    // fused GATv2 edge phase -> g_hpre (head-mean + conv bias, tf32-rounded)
    k_node<<<NNODES, 256>>>(att, bias);

    // h = g_hpre @ Wfc + bfc -> d_out[0 : N*NC]
    {
        dim3 grid((NCLS + 127) / 128, (NNODES + 255) / 256);
        k_gemm<<<grid, 256, 98304>>>(1, NNODES, NCLS, NCLS, bfc, bfc, out);
    }

    // pass-throughs (guarded by out_size so we can never write past d_out)
    size_t offh = (size_t)NNODES * NCLS;
    size_t nE   = (size_t)in_sizes[10];
    size_t nC   = (size_t)in_sizes[11];
    if ((size_t)out_size >= offh + nE) {
        cudaMemcpyAsync(out + offh, exps, nE * sizeof(float),
                        cudaMemcpyDeviceToDevice, 0);
        if ((size_t)out_size >= offh + nE + nC)
            cudaMemcpyAsync(out + offh + nE, exps_c, nC * sizeof(float),
                            cudaMemcpyDeviceToDevice, 0);
    }
}

// round 11
// speedup vs baseline: 1.0585x; 1.0585x over previous
#include <cuda_runtime.h>
#include <cstdint>

#define NNODES 10000
#define NEDGES 100000
#define ET     (NEDGES + NNODES)
#define KDIM   1024
#define HEADS  3
#define CH     1024
#define HC     3072   // HEADS*CH
#define HC2    6144   // 2*HC
#define NCLS   460
#define NEG    0.2f
#define SMAX   1024

// ---------------- device scratch (no allocation allowed) ----------------
__device__ float g_xlr[(size_t)NNODES * HC2];   // [N, xl(3072) | xr(3072)]
__device__ float g_hpre[(size_t)NNODES * KDIM]; // aggregated (+bias, /H), tf32-rounded
__device__ float g_xc[(size_t)NNODES * KDIM];   // tf32(x)
__device__ float g_wc[(size_t)KDIM * HC2];      // tf32([Wl|Wr]) merged, row-major [K,6144]
__device__ float g_wfc[(size_t)KDIM * NCLS];    // tf32(Wfc)
__device__ int   g_deg[NNODES];
__device__ int   g_off[NNODES + 1];
__device__ int   g_cur[NNODES];
__device__ int   g_csrc[ET];
__device__ int   g_is64;

// ---------------- helpers ----------------
__device__ __forceinline__ float ftf32(float x) {
    float r;
    asm("cvt.rna.tf32.f32 %0, %1;" : "=f"(r) : "f"(x));
    return r;
}

__device__ __forceinline__ void cpa16(uint32_t dst, const float* src, bool p) {
    asm volatile("cp.async.cg.shared.global [%0], [%1], 16, %2;\n"
                 :: "r"(dst), "l"(src), "r"(p ? 16 : 0));
}

// ---------------- edge_index dtype detection (parallel) ----------------
// JAX without x64 silently stores int64-annotated arrays as int32. Interpret
// the first 1000 words as int64: genuine int64 node ids are all in [0, N);
// int32 data packed two-per-word lands out of range almost surely.
__global__ void k_detect(const long long* __restrict__ ei64) {
    __shared__ int bad;
    if (threadIdx.x == 0) bad = 0;
    __syncthreads();
    for (int i = threadIdx.x; i < 1000; i += 256) {
        long long v = ei64[i];
        if (v < 0 || v >= NNODES) bad = 1;  // benign race
    }
    __syncthreads();
    if (threadIdx.x == 0) g_is64 = bad ? 0 : 1;
}

__device__ __forceinline__ int clampN(int v) {
    return v < 0 ? 0 : (v >= NNODES ? NNODES - 1 : v);
}

// ---------------- CSR build (by destination) ----------------
__global__ void k_zero() {
    int i = blockIdx.x * blockDim.x + threadIdx.x;
    if (i < NNODES) g_deg[i] = 0;
}

__global__ void k_deg(const long long* __restrict__ e64,
                      const int* __restrict__ e32) {
    int i = blockIdx.x * blockDim.x + threadIdx.x;
    if (i >= ET) return;
    int dst;
    if (i < NEDGES) dst = clampN(g_is64 ? (int)e64[2 * i + 1] : e32[2 * i + 1]);
    else            dst = i - NEDGES;
    atomicAdd(&g_deg[dst], 1);
}

// coarsened single-pass scan: 1024 threads x 10 elements
__global__ void k_scan() {
    __shared__ int wt[32];
    const int tid = threadIdx.x, lane = tid & 31, warp = tid >> 5;
    const int PER = 10;
    int base = tid * PER;
    int v[PER];
    int run = 0;
#pragma unroll
    for (int t = 0; t < PER; t++) {
        int idx = base + t;
        int d = (idx < NNODES) ? g_deg[idx] : 0;
        run += d; v[t] = run;
    }
    int ws = run;
#pragma unroll
    for (int o = 1; o < 32; o <<= 1) {
        int t = __shfl_up_sync(0xffffffffu, ws, o);
        if (lane >= o) ws += t;
    }
    if (lane == 31) wt[warp] = ws;
    __syncthreads();
    if (warp == 0) {
        int t = wt[lane];
#pragma unroll
        for (int o = 1; o < 32; o <<= 1) {
            int u = __shfl_up_sync(0xffffffffu, t, o);
            if (lane >= o) t += u;
        }
        wt[lane] = t;
    }
    __syncthreads();
    int off = (warp ? wt[warp - 1] : 0) + (ws - run);
#pragma unroll
    for (int t = 0; t < PER; t++) {
        int idx = base + t;
        if (idx < NNODES) {
            int d = v[t] - (t ? v[t - 1] : 0);
            g_off[idx + 1] = off + v[t];
            g_cur[idx]     = off + v[t] - d;
        }
    }
    if (tid == 0) g_off[0] = 0;
}

__global__ void k_fill(const long long* __restrict__ e64,
                       const int* __restrict__ e32) {
    int i = blockIdx.x * blockDim.x + threadIdx.x;
    if (i >= ET) return;
    int src, dst;
    if (i < NEDGES) {
        if (g_is64) { src = (int)e64[2 * i]; dst = (int)e64[2 * i + 1]; }
        else        { src = e32[2 * i];      dst = e32[2 * i + 1]; }
        src = clampN(src); dst = clampN(dst);
    } else {
        src = i - NEDGES; dst = src;
    }
    int pos = atomicAdd(&g_cur[dst], 1);
    if (pos >= 0 && pos < ET) g_csrc[pos] = src;
}

// ---------------- pre-convert operands to tf32 (rna) ----------------
__global__ void k_cvtX(const float* __restrict__ x) {
    int i = blockIdx.x * blockDim.x + threadIdx.x;
    if (i >= NNODES * KDIM / 4) return;
    float4 v = ((const float4*)x)[i];
    v.x = ftf32(v.x); v.y = ftf32(v.y); v.z = ftf32(v.z); v.w = ftf32(v.w);
    ((float4*)g_xc)[i] = v;
}

__global__ void k_cvtW(const float* __restrict__ Wl, const float* __restrict__ Wr) {
    int i = blockIdx.x * blockDim.x + threadIdx.x;
    if (i >= KDIM * HC2 / 4) return;
    int k  = i / (HC2 / 4);
    int c4 = i - k * (HC2 / 4);
    float4 v = (c4 < HC / 4)
        ? ((const float4*)Wl)[(size_t)k * (HC / 4) + c4]
        : ((const float4*)Wr)[(size_t)k * (HC / 4) + (c4 - HC / 4)];
    v.x = ftf32(v.x); v.y = ftf32(v.y); v.z = ftf32(v.z); v.w = ftf32(v.w);
    ((float4*)g_wc)[i] = v;
}

__global__ void k_cvtF(const float* __restrict__ Wfc) {
    int i = blockIdx.x * blockDim.x + threadIdx.x;
    if (i >= KDIM * NCLS / 4) return;
    float4 v = ((const float4*)Wfc)[i];
    v.x = ftf32(v.x); v.y = ftf32(v.y); v.z = ftf32(v.z); v.w = ftf32(v.w);
    ((float4*)g_wfc)[i] = v;
}

// ---------------- cp.async double-buffered tf32 GEMM, 128x128 tiles ----------------
// mode 0: C[g_xlr] = g_xc[M,K] @ g_wc[K,6144] + (bl|br)
// mode 1: Cout     = g_hpre[M,K] @ g_wfc[K,460] + bfc
__global__ __launch_bounds__(256) void k_gemm(
    int mode, int M, int Ntot, int nsplit,
    const float* __restrict__ bias1, const float* __restrict__ bias2,
    float* __restrict__ Cout)
{
    extern __shared__ float smem[];
    float* As = smem;          // 2 stages x 4096 floats
    float* Bs = smem + 8192;   // 2 stages x 4096 floats

    const float* Ap = mode ? g_hpre : g_xc;
    const float* Bp = mode ? g_wfc : g_wc;
    float* Cp = mode ? Cout : g_xlr;
    const int K = KDIM, ldb = Ntot, ldc = Ntot;

    const int tid  = threadIdx.x;
    const int lane = tid & 31, warp = tid >> 5;
    const int wm = warp >> 2, wn = warp & 3;       // 2 x 4 warp grid
    const int g  = lane >> 2, tg = lane & 3;
    const int m0 = blockIdx.y * 128, n0 = blockIdx.x * 128;

    const int ar  = tid >> 3;        // A row 0..31 (+i*32)
    const int akc = (tid & 7) * 4;   // A k-chunk
    const int bkr = tid >> 5;        // B k row 0..7 (+i*8)
    const int bnc = (tid & 31) * 4;  // B n-chunk

    const uint32_t sb = (uint32_t)__cvta_generic_to_shared(smem);

#define ISSUE(k0, st) do {                                                      \
    _Pragma("unroll")                                                           \
    for (int i = 0; i < 4; i++) {                                               \
        int r = ar + i * 32; int gm = m0 + r;                                   \
        const float* src = Ap + (size_t)(gm < M ? gm : 0) * K + (k0) + akc;     \
        uint32_t d = sb + (((st) * 4096 + r * 32 + (akc ^ ((r & 7) << 2))) << 2); \
        cpa16(d, src, gm < M);                                                  \
    }                                                                           \
    _Pragma("unroll")                                                           \
    for (int i = 0; i < 4; i++) {                                               \
        int kr = bkr + i * 8; int gn = n0 + bnc; bool ok = gn < Ntot;           \
        const float* src = Bp + (size_t)((k0) + kr) * ldb + (ok ? gn : 0);      \
        uint32_t d = sb + ((8192 + (st) * 4096 + kr * 128 + (bnc ^ ((kr & 3) << 3))) << 2); \
        cpa16(d, src, ok);                                                      \
    }                                                                           \
} while (0)

    float acc[4][4][4];
#pragma unroll
    for (int a = 0; a < 4; a++)
#pragma unroll
        for (int b = 0; b < 4; b++)
#pragma unroll
            for (int c = 0; c < 4; c++) acc[a][b][c] = 0.f;

    ISSUE(0, 0);
    asm volatile("cp.async.commit_group;\n");

    const int niter = K / 32;
    for (int it = 0; it < niter; it++) {
        if (it + 1 < niter) {
            ISSUE((it + 1) * 32, (it + 1) & 1);
            asm volatile("cp.async.commit_group;\n");
            asm volatile("cp.async.wait_group 1;\n");
        } else {
            asm volatile("cp.async.wait_group 0;\n");
        }
        __syncthreads();

        const float* A0 = As + (it & 1) * 4096;
        const float* B0 = Bs + (it & 1) * 4096;
#pragma unroll
        for (int kk = 0; kk < 4; kk++) {
            const int kb = kk * 8;
            uint32_t af[4][4];
            uint32_t bf[4][2];
#pragma unroll
            for (int mi = 0; mi < 4; mi++) {
                int r0 = wm * 64 + mi * 16 + g;
                int r1 = r0 + 8;
                int k1 = kb + tg, k2 = k1 + 4;
                af[mi][0] = __float_as_uint(A0[r0 * 32 + (k1 ^ ((r0 & 7) << 2))]);
                af[mi][1] = __float_as_uint(A0[r1 * 32 + (k1 ^ ((r1 & 7) << 2))]);
                af[mi][2] = __float_as_uint(A0[r0 * 32 + (k2 ^ ((r0 & 7) << 2))]);
                af[mi][3] = __float_as_uint(A0[r1 * 32 + (k2 ^ ((r1 & 7) << 2))]);
            }
#pragma unroll
            for (int ni = 0; ni < 4; ni++) {
                int n = wn * 32 + ni * 8 + g;
                int k1 = kb + tg, k2 = k1 + 4;
                bf[ni][0] = __float_as_uint(B0[k1 * 128 + (n ^ ((k1 & 3) << 3))]);
                bf[ni][1] = __float_as_uint(B0[k2 * 128 + (n ^ ((k2 & 3) << 3))]);
            }
#pragma unroll
            for (int mi = 0; mi < 4; mi++)
#pragma unroll
                for (int ni = 0; ni < 4; ni++)
                    asm volatile(
                        "mma.sync.aligned.m16n8k8.row.col.f32.tf32.tf32.f32 "
                        "{%0,%1,%2,%3}, {%4,%5,%6,%7}, {%8,%9}, {%0,%1,%2,%3};\n"
                        : "+f"(acc[mi][ni][0]), "+f"(acc[mi][ni][1]),
                          "+f"(acc[mi][ni][2]), "+f"(acc[mi][ni][3])
                        : "r"(af[mi][0]), "r"(af[mi][1]), "r"(af[mi][2]), "r"(af[mi][3]),
                          "r"(bf[ni][0]), "r"(bf[ni][1]));
        }
        __syncthreads();
    }
#undef ISSUE

    // epilogue: c0 (g, 2tg), c1 (g, 2tg+1), c2/c3 at row+8
#pragma unroll
    for (int mi = 0; mi < 4; mi++) {
        int row0 = m0 + wm * 64 + mi * 16 + g;
#pragma unroll
        for (int ni = 0; ni < 4; ni++) {
            int col = n0 + wn * 32 + ni * 8 + tg * 2;
            if (col < Ntot) {
                float b0, b1;
                if (col < nsplit) { b0 = bias1[col]; b1 = bias1[col + 1]; }
                else              { b0 = bias2[col - nsplit]; b1 = bias2[col - nsplit + 1]; }
                if (row0 < M) {
                    float2 o = make_float2(acc[mi][ni][0] + b0, acc[mi][ni][1] + b1);
                    *(float2*)(Cp + (size_t)row0 * ldc + col) = o;
                }
                int row1 = row0 + 8;
                if (row1 < M) {
                    float2 o = make_float2(acc[mi][ni][2] + b0, acc[mi][ni][3] + b1);
                    *(float2*)(Cp + (size_t)row1 * ldc + col) = o;
                }
            }
        }
    }
}

// ---------------- fused online-softmax node kernel ----------------
// One block per node; each xl[j] row read exactly once; 1 barrier per edge
// (parity double-buffered warp partials).
__global__ __launch_bounds__(256) void k_node(const float* __restrict__ att,
                                              const float* __restrict__ bias)
{
    __shared__ int   ssrc[SMAX];
    __shared__ float wred[2][24];

    const int n    = blockIdx.x;
    const int tid  = threadIdx.x;
    const int lane = tid & 31, warp = tid >> 5;
    const int s    = g_off[n];
    const int deg  = g_off[n + 1] - s;
    const bool insm = (deg <= SMAX);

    // xr[n] and att live entirely in registers (each thread owns 4 ch/head)
    const float4* xr4 = (const float4*)(g_xlr + (size_t)n * HC2 + HC);
    float4 r0 = __ldg(xr4 + tid), r1 = __ldg(xr4 + tid + 256), r2 = __ldg(xr4 + tid + 512);
    const float4* at4 = (const float4*)att;
    float4 a0 = at4[tid], a1 = at4[tid + 256], a2 = at4[tid + 512];

    for (int i = tid; i < deg && i < SMAX; i += 256) ssrc[i] = g_csrc[s + i];
    __syncthreads();
    // deterministic order: sort srcs ascending (deg ~11)
    if (tid == 0 && insm && deg > 1) {
        for (int i = 1; i < deg; i++) {
            int v = ssrc[i]; int j = i - 1;
            while (j >= 0 && ssrc[j] > v) { ssrc[j + 1] = ssrc[j]; j--; }
            ssrc[j + 1] = v;
        }
    }
    __syncthreads();

    float m0 = -1e30f, m1 = -1e30f, m2 = -1e30f;
    float d0 = 0.f,   d1 = 0.f,   d2 = 0.f;
    float4 A0 = make_float4(0.f, 0.f, 0.f, 0.f);
    float4 A1 = A0, A2 = A0;

    // prefetch edge 0
    int j0 = insm ? ssrc[0] : g_csrc[s];
    const float4* p = (const float4*)(g_xlr + (size_t)j0 * HC2);
    float4 v0 = __ldg(p + tid), v1 = __ldg(p + tid + 256), v2 = __ldg(p + tid + 512);

    for (int i = 0; i < deg; i++) {
        float4 c0 = v0, c1 = v1, c2 = v2;
        if (i + 1 < deg) {
            int j2 = insm ? ssrc[i + 1] : g_csrc[s + i + 1];
            const float4* p2 = (const float4*)(g_xlr + (size_t)j2 * HC2);
            v0 = __ldg(p2 + tid); v1 = __ldg(p2 + tid + 256); v2 = __ldg(p2 + tid + 512);
        }
        // per-thread partial score per head
        float p0, p1, p2s, t;
        t = c0.x + r0.x; t = t > 0.f ? t : NEG * t; p0  = t * a0.x;
        t = c0.y + r0.y; t = t > 0.f ? t : NEG * t; p0 += t * a0.y;
        t = c0.z + r0.z; t = t > 0.f ? t : NEG * t; p0 += t * a0.z;
        t = c0.w + r0.w; t = t > 0.f ? t : NEG * t; p0 += t * a0.w;
        t = c1.x + r1.x; t = t > 0.f ? t : NEG * t; p1  = t * a1.x;
        t = c1.y + r1.y; t = t > 0.f ? t : NEG * t; p1 += t * a1.y;
        t = c1.z + r1.z; t = t > 0.f ? t : NEG * t; p1 += t * a1.z;
        t = c1.w + r1.w; t = t > 0.f ? t : NEG * t; p1 += t * a1.w;
        t = c2.x + r2.x; t = t > 0.f ? t : NEG * t; p2s  = t * a2.x;
        t = c2.y + r2.y; t = t > 0.f ? t : NEG * t; p2s += t * a2.y;
        t = c2.z + r2.z; t = t > 0.f ? t : NEG * t; p2s += t * a2.z;
        t = c2.w + r2.w; t = t > 0.f ? t : NEG * t; p2s += t * a2.w;
#pragma unroll
        for (int o = 16; o; o >>= 1) {
            p0  += __shfl_xor_sync(0xffffffffu, p0,  o);
            p1  += __shfl_xor_sync(0xffffffffu, p1,  o);
            p2s += __shfl_xor_sync(0xffffffffu, p2s, o);
        }
        float* wb = wred[i & 1];
        if (lane == 0) {
            wb[warp * 3]     = p0;
            wb[warp * 3 + 1] = p1;
            wb[warp * 3 + 2] = p2s;
        }
        __syncthreads();
        float s0 = 0.f, s1 = 0.f, s2 = 0.f;
#pragma unroll
        for (int w = 0; w < 8; w++) {
            s0 += wb[w * 3]; s1 += wb[w * 3 + 1]; s2 += wb[w * 3 + 2];
        }

        // online softmax update (redundant per thread, identical results)
        float mn, sc, e;
        mn = fmaxf(m0, s0); sc = __expf(m0 - mn); e = __expf(s0 - mn);
        d0 = d0 * sc + e; m0 = mn;
        A0.x = A0.x * sc + e * c0.x; A0.y = A0.y * sc + e * c0.y;
        A0.z = A0.z * sc + e * c0.z; A0.w = A0.w * sc + e * c0.w;
        mn = fmaxf(m1, s1); sc = __expf(m1 - mn); e = __expf(s1 - mn);
        d1 = d1 * sc + e; m1 = mn;
        A1.x = A1.x * sc + e * c1.x; A1.y = A1.y * sc + e * c1.y;
        A1.z = A1.z * sc + e * c1.z; A1.w = A1.w * sc + e * c1.w;
        mn = fmaxf(m2, s2); sc = __expf(m2 - mn); e = __expf(s2 - mn);
        d2 = d2 * sc + e; m2 = mn;
        A2.x = A2.x * sc + e * c2.x; A2.y = A2.y * sc + e * c2.y;
        A2.z = A2.z * sc + e * c2.z; A2.w = A2.w * sc + e * c2.w;
    }

    float i0 = 1.f / (d0 + 1e-16f);
    float i1 = 1.f / (d1 + 1e-16f);
    float i2 = 1.f / (d2 + 1e-16f);
    const float third = 1.f / 3.f;
    float4 bb = ((const float4*)bias)[tid];
    float4 o;
    o.x = ftf32((A0.x * i0 + A1.x * i1 + A2.x * i2) * third + bb.x);
    o.y = ftf32((A0.y * i0 + A1.y * i1 + A2.y * i2) * third + bb.y);
    o.z = ftf32((A0.z * i0 + A1.z * i1 + A2.z * i2) * third + bb.z);
    o.w = ftf32((A0.w * i0 + A1.w * i1 + A2.w * i2) * third + bb.w);
    ((float4*)(g_hpre + (size_t)n * KDIM))[tid] = o;
}

// ---------------- launch ----------------
extern "C" void kernel_launch(void* const* d_in, const int* in_sizes, int n_in,
                              void* d_out, int out_size) {
    (void)n_in;
    const float*     x      = (const float*)d_in[0];
    const long long* e64    = (const long long*)d_in[1];
    const int*       e32    = (const int*)d_in[1];
    const float*     Wl     = (const float*)d_in[2];
    const float*     bl     = (const float*)d_in[3];
    const float*     Wr     = (const float*)d_in[4];
    const float*     br     = (const float*)d_in[5];
    const float*     att    = (const float*)d_in[6];
    const float*     bias   = (const float*)d_in[7];
    const float*     Wfc    = (const float*)d_in[8];
    const float*     bfc    = (const float*)d_in[9];
    const float*     exps   = (const float*)d_in[10];
    const float*     exps_c = (const float*)d_in[11];
    float* out = (float*)d_out;

    cudaFuncSetAttribute(k_gemm, cudaFuncAttributeMaxDynamicSharedMemorySize, 65536);

    // detect int32 vs int64 edge_index, then CSR build (by destination)
    k_detect<<<1, 256>>>(e64);
    k_zero<<<(NNODES + 255) / 256, 256>>>();
    k_deg<<<(ET + 255) / 256, 256>>>(e64, e32);
    k_scan<<<1, 1024>>>();
    k_fill<<<(ET + 255) / 256, 256>>>(e64, e32);

    // pre-convert operands to tf32 (rna)
    k_cvtX<<<(NNODES * KDIM / 4 + 255) / 256, 256>>>(x);
    k_cvtW<<<(KDIM * HC2 / 4 + 255) / 256, 256>>>(Wl, Wr);
    k_cvtF<<<(KDIM * NCLS / 4 + 255) / 256, 256>>>(Wfc);

    // xl | xr = x @ [Wl | Wr] + [bl | br]   -> g_xlr
    {
        dim3 grid(HC2 / 128, (NNODES + 127) / 128);
        k_gemm<<<grid, 256, 65536>>>(0, NNODES, HC2, HC, bl, br, nullptr);
    }

    // fused GATv2 edge phase -> g_hpre (head-mean + conv bias, tf32-rounded)
    k_node<<<NNODES, 256>>>(att, bias);

    // h = g_hpre @ Wfc + bfc -> d_out[0 : N*NC]
    {
        dim3 grid((NCLS + 127) / 128, (NNODES + 127) / 128);
        k_gemm<<<grid, 256, 65536>>>(1, NNODES, NCLS, NCLS, bfc, bfc, out);
    }

    // pass-throughs (guarded by out_size so we can never write past d_out)
    size_t offh = (size_t)NNODES * NCLS;
    size_t nE   = (size_t)in_sizes[10];
    size_t nC   = (size_t)in_sizes[11];
    if ((size_t)out_size >= offh + nE) {
        cudaMemcpyAsync(out + offh, exps, nE * sizeof(float),
                        cudaMemcpyDeviceToDevice, 0);
        if ((size_t)out_size >= offh + nE + nC)
            cudaMemcpyAsync(out + offh + nE, exps_c, nC * sizeof(float),
                            cudaMemcpyDeviceToDevice, 0);
    }
}

// round 17
// speedup vs baseline: 1.1133x; 1.0518x over previous
#include <cuda_runtime.h>
#include <cstdint>

#define NNODES 10000
#define NEDGES 100000
#define ET     (NEDGES + NNODES)
#define KDIM   1024
#define HEADS  3
#define CH     1024
#define HC     3072   // HEADS*CH
#define HC2    6144   // 2*HC
#define NCLS   460
#define NEG    0.2f
#define SMAX   1024

// ---------------- device scratch (no allocation allowed) ----------------
__device__ float g_xl[(size_t)NNODES * HC];     // xl projections (L2-resident set)
__device__ float g_xr[(size_t)NNODES * HC];     // xr projections (streamed once)
__device__ float g_hpre[(size_t)NNODES * KDIM]; // aggregated (+bias, /H), tf32-rounded
__device__ float g_xc[(size_t)NNODES * KDIM];   // tf32(x)
__device__ float g_wc[(size_t)KDIM * HC2];      // tf32([Wl|Wr]) merged, row-major [K,6144]
__device__ float g_wfc[(size_t)KDIM * NCLS];    // tf32(Wfc)
__device__ int   g_deg[NNODES];
__device__ int   g_off[NNODES + 1];
__device__ int   g_cur[NNODES];
__device__ int   g_csrc[ET];
__device__ int   g_is64;

// ---------------- helpers ----------------
__device__ __forceinline__ float ftf32(float x) {
    float r;
    asm("cvt.rna.tf32.f32 %0, %1;" : "=f"(r) : "f"(x));
    return r;
}

__device__ __forceinline__ void cpa16(uint32_t dst, const float* src, bool p) {
    asm volatile("cp.async.cg.shared.global [%0], [%1], 16, %2;\n"
                 :: "r"(dst), "l"(src), "r"(p ? 16 : 0));
}

// 256-bit loads with L2 residency hints (sm_103 requires .v8.b32 for hints)
__device__ __forceinline__ void ld8_el(const float* p, float* o) {
    uint32_t u0,u1,u2,u3,u4,u5,u6,u7;
    asm("ld.global.nc.L2::evict_last.v8.b32 {%0,%1,%2,%3,%4,%5,%6,%7}, [%8];"
        : "=r"(u0),"=r"(u1),"=r"(u2),"=r"(u3),
          "=r"(u4),"=r"(u5),"=r"(u6),"=r"(u7) : "l"(p));
    o[0]=__uint_as_float(u0); o[1]=__uint_as_float(u1);
    o[2]=__uint_as_float(u2); o[3]=__uint_as_float(u3);
    o[4]=__uint_as_float(u4); o[5]=__uint_as_float(u5);
    o[6]=__uint_as_float(u6); o[7]=__uint_as_float(u7);
}
__device__ __forceinline__ void ld8_ef(const float* p, float* o) {
    uint32_t u0,u1,u2,u3,u4,u5,u6,u7;
    asm("ld.global.nc.L2::evict_first.v8.b32 {%0,%1,%2,%3,%4,%5,%6,%7}, [%8];"
        : "=r"(u0),"=r"(u1),"=r"(u2),"=r"(u3),
          "=r"(u4),"=r"(u5),"=r"(u6),"=r"(u7) : "l"(p));
    o[0]=__uint_as_float(u0); o[1]=__uint_as_float(u1);
    o[2]=__uint_as_float(u2); o[3]=__uint_as_float(u3);
    o[4]=__uint_as_float(u4); o[5]=__uint_as_float(u5);
    o[6]=__uint_as_float(u6); o[7]=__uint_as_float(u7);
}

// ---------------- edge_index dtype detection (parallel) ----------------
__global__ void k_detect(const long long* __restrict__ ei64) {
    __shared__ int bad;
    if (threadIdx.x == 0) bad = 0;
    __syncthreads();
    for (int i = threadIdx.x; i < 1000; i += 256) {
        long long v = ei64[i];
        if (v < 0 || v >= NNODES) bad = 1;  // benign race
    }
    __syncthreads();
    if (threadIdx.x == 0) g_is64 = bad ? 0 : 1;
}

__device__ __forceinline__ int clampN(int v) {
    return v < 0 ? 0 : (v >= NNODES ? NNODES - 1 : v);
}

// ---------------- CSR build (by destination) ----------------
__global__ void k_zero() {
    int i = blockIdx.x * blockDim.x + threadIdx.x;
    if (i < NNODES) g_deg[i] = 0;
}

__global__ void k_deg(const long long* __restrict__ e64,
                      const int* __restrict__ e32) {
    int i = blockIdx.x * blockDim.x + threadIdx.x;
    if (i >= ET) return;
    int dst;
    if (i < NEDGES) dst = clampN(g_is64 ? (int)e64[2 * i + 1] : e32[2 * i + 1]);
    else            dst = i - NEDGES;
    atomicAdd(&g_deg[dst], 1);
}

// coarsened single-pass scan: 1024 threads x 10 elements
__global__ void k_scan() {
    __shared__ int wt[32];
    const int tid = threadIdx.x, lane = tid & 31, warp = tid >> 5;
    const int PER = 10;
    int base = tid * PER;
    int v[PER];
    int run = 0;
#pragma unroll
    for (int t = 0; t < PER; t++) {
        int idx = base + t;
        int d = (idx < NNODES) ? g_deg[idx] : 0;
        run += d; v[t] = run;
    }
    int ws = run;
#pragma unroll
    for (int o = 1; o < 32; o <<= 1) {
        int t = __shfl_up_sync(0xffffffffu, ws, o);
        if (lane >= o) ws += t;
    }
    if (lane == 31) wt[warp] = ws;
    __syncthreads();
    if (warp == 0) {
        int t = wt[lane];
#pragma unroll
        for (int o = 1; o < 32; o <<= 1) {
            int u = __shfl_up_sync(0xffffffffu, t, o);
            if (lane >= o) t += u;
        }
        wt[lane] = t;
    }
    __syncthreads();
    int off = (warp ? wt[warp - 1] : 0) + (ws - run);
#pragma unroll
    for (int t = 0; t < PER; t++) {
        int idx = base + t;
        if (idx < NNODES) {
            int d = v[t] - (t ? v[t - 1] : 0);
            g_off[idx + 1] = off + v[t];
            g_cur[idx]     = off + v[t] - d;
        }
    }
    if (tid == 0) g_off[0] = 0;
}

__global__ void k_fill(const long long* __restrict__ e64,
                       const int* __restrict__ e32) {
    int i = blockIdx.x * blockDim.x + threadIdx.x;
    if (i >= ET) return;
    int src, dst;
    if (i < NEDGES) {
        if (g_is64) { src = (int)e64[2 * i]; dst = (int)e64[2 * i + 1]; }
        else        { src = e32[2 * i];      dst = e32[2 * i + 1]; }
        src = clampN(src); dst = clampN(dst);
    } else {
        src = i - NEDGES; dst = src;
    }
    int pos = atomicAdd(&g_cur[dst], 1);
    if (pos >= 0 && pos < ET) g_csrc[pos] = src;
}

// ---------------- pre-convert operands to tf32 (rna) ----------------
__global__ void k_cvtX(const float* __restrict__ x) {
    int i = blockIdx.x * blockDim.x + threadIdx.x;
    if (i >= NNODES * KDIM / 4) return;
    float4 v = ((const float4*)x)[i];
    v.x = ftf32(v.x); v.y = ftf32(v.y); v.z = ftf32(v.z); v.w = ftf32(v.w);
    ((float4*)g_xc)[i] = v;
}

__global__ void k_cvtW(const float* __restrict__ Wl, const float* __restrict__ Wr) {
    int i = blockIdx.x * blockDim.x + threadIdx.x;
    if (i >= KDIM * HC2 / 4) return;
    int k  = i / (HC2 / 4);
    int c4 = i - k * (HC2 / 4);
    float4 v = (c4 < HC / 4)
        ? ((const float4*)Wl)[(size_t)k * (HC / 4) + c4]
        : ((const float4*)Wr)[(size_t)k * (HC / 4) + (c4 - HC / 4)];
    v.x = ftf32(v.x); v.y = ftf32(v.y); v.z = ftf32(v.z); v.w = ftf32(v.w);
    ((float4*)g_wc)[i] = v;
}

__global__ void k_cvtF(const float* __restrict__ Wfc) {
    int i = blockIdx.x * blockDim.x + threadIdx.x;
    if (i >= KDIM * NCLS / 4) return;
    float4 v = ((const float4*)Wfc)[i];
    v.x = ftf32(v.x); v.y = ftf32(v.y); v.z = ftf32(v.z); v.w = ftf32(v.w);
    ((float4*)g_wfc)[i] = v;
}

// ---------------- cp.async double-buffered tf32 GEMM, 128x128 tiles ----------------
// mode 0: g_xl|g_xr = g_xc[M,K] @ g_wc[K,6144] + (bl|br)   (split columns at HC)
// mode 1: Cout      = g_hpre[M,K] @ g_wfc[K,460] + bfc
__global__ __launch_bounds__(256) void k_gemm(
    int mode, int M, int Ntot, int nsplit,
    const float* __restrict__ bias1, const float* __restrict__ bias2,
    float* __restrict__ Cout)
{
    extern __shared__ float smem[];
    float* As = smem;          // 2 stages x 4096 floats
    float* Bs = smem + 8192;   // 2 stages x 4096 floats

    const float* Ap = mode ? g_hpre : g_xc;
    const float* Bp = mode ? g_wfc : g_wc;
    const int K = KDIM, ldb = Ntot;

    const int tid  = threadIdx.x;
    const int lane = tid & 31, warp = tid >> 5;
    const int wm = warp >> 2, wn = warp & 3;       // 2 x 4 warp grid
    const int g  = lane >> 2, tg = lane & 3;
    const int m0 = blockIdx.y * 128, n0 = blockIdx.x * 128;

    const int ar  = tid >> 3;        // A row 0..31 (+i*32)
    const int akc = (tid & 7) * 4;   // A k-chunk
    const int bkr = tid >> 5;        // B k row 0..7 (+i*8)
    const int bnc = (tid & 31) * 4;  // B n-chunk

    const uint32_t sb = (uint32_t)__cvta_generic_to_shared(smem);

#define ISSUE(k0, st) do {                                                      \
    _Pragma("unroll")                                                           \
    for (int i = 0; i < 4; i++) {                                               \
        int r = ar + i * 32; int gm = m0 + r;                                   \
        const float* src = Ap + (size_t)(gm < M ? gm : 0) * K + (k0) + akc;     \
        uint32_t d = sb + (((st) * 4096 + r * 32 + (akc ^ ((r & 7) << 2))) << 2); \
        cpa16(d, src, gm < M);                                                  \
    }                                                                           \
    _Pragma("unroll")                                                           \
    for (int i = 0; i < 4; i++) {                                               \
        int kr = bkr + i * 8; int gn = n0 + bnc; bool ok = gn < Ntot;           \
        const float* src = Bp + (size_t)((k0) + kr) * ldb + (ok ? gn : 0);      \
        uint32_t d = sb + ((8192 + (st) * 4096 + kr * 128 + (bnc ^ ((kr & 3) << 3))) << 2); \
        cpa16(d, src, ok);                                                      \
    }                                                                           \
} while (0)

    float acc[4][4][4];
#pragma unroll
    for (int a = 0; a < 4; a++)
#pragma unroll
        for (int b = 0; b < 4; b++)
#pragma unroll
            for (int c = 0; c < 4; c++) acc[a][b][c] = 0.f;

    ISSUE(0, 0);
    asm volatile("cp.async.commit_group;\n");

    const int niter = K / 32;
    for (int it = 0; it < niter; it++) {
        if (it + 1 < niter) {
            ISSUE((it + 1) * 32, (it + 1) & 1);
            asm volatile("cp.async.commit_group;\n");
            asm volatile("cp.async.wait_group 1;\n");
        } else {
            asm volatile("cp.async.wait_group 0;\n");
        }
        __syncthreads();

        const float* A0 = As + (it & 1) * 4096;
        const float* B0 = Bs + (it & 1) * 4096;
#pragma unroll
        for (int kk = 0; kk < 4; kk++) {
            const int kb = kk * 8;
            uint32_t af[4][4];
            uint32_t bf[4][2];
#pragma unroll
            for (int mi = 0; mi < 4; mi++) {
                int r0 = wm * 64 + mi * 16 + g;
                int r1 = r0 + 8;
                int k1 = kb + tg, k2 = k1 + 4;
                af[mi][0] = __float_as_uint(A0[r0 * 32 + (k1 ^ ((r0 & 7) << 2))]);
                af[mi][1] = __float_as_uint(A0[r1 * 32 + (k1 ^ ((r1 & 7) << 2))]);
                af[mi][2] = __float_as_uint(A0[r0 * 32 + (k2 ^ ((r0 & 7) << 2))]);
                af[mi][3] = __float_as_uint(A0[r1 * 32 + (k2 ^ ((r1 & 7) << 2))]);
            }
#pragma unroll
            for (int ni = 0; ni < 4; ni++) {
                int n = wn * 32 + ni * 8 + g;
                int k1 = kb + tg, k2 = k1 + 4;
                bf[ni][0] = __float_as_uint(B0[k1 * 128 + (n ^ ((k1 & 3) << 3))]);
                bf[ni][1] = __float_as_uint(B0[k2 * 128 + (n ^ ((k2 & 3) << 3))]);
            }
#pragma unroll
            for (int mi = 0; mi < 4; mi++)
#pragma unroll
                for (int ni = 0; ni < 4; ni++)
                    asm volatile(
                        "mma.sync.aligned.m16n8k8.row.col.f32.tf32.tf32.f32 "
                        "{%0,%1,%2,%3}, {%4,%5,%6,%7}, {%8,%9}, {%0,%1,%2,%3};\n"
                        : "+f"(acc[mi][ni][0]), "+f"(acc[mi][ni][1]),
                          "+f"(acc[mi][ni][2]), "+f"(acc[mi][ni][3])
                        : "r"(af[mi][0]), "r"(af[mi][1]), "r"(af[mi][2]), "r"(af[mi][3]),
                          "r"(bf[ni][0]), "r"(bf[ni][1]));
        }
        __syncthreads();
    }
#undef ISSUE

    // epilogue: c0 (g, 2tg), c1 (g, 2tg+1), c2/c3 at row+8
#pragma unroll
    for (int mi = 0; mi < 4; mi++) {
        int row0 = m0 + wm * 64 + mi * 16 + g;
#pragma unroll
        for (int ni = 0; ni < 4; ni++) {
            int col = n0 + wn * 32 + ni * 8 + tg * 2;
            if (col < Ntot) {
                float b0, b1;
                if (col < nsplit) { b0 = bias1[col]; b1 = bias1[col + 1]; }
                else              { b0 = bias2[col - nsplit]; b1 = bias2[col - nsplit + 1]; }
                float *p0, *p1;
                if (mode) {
                    p0 = Cout + (size_t)row0 * Ntot + col;
                    p1 = Cout + (size_t)(row0 + 8) * Ntot + col;
                } else if (col < HC) {
                    p0 = g_xl + (size_t)row0 * HC + col;
                    p1 = g_xl + (size_t)(row0 + 8) * HC + col;
                } else {
                    p0 = g_xr + (size_t)row0 * HC + (col - HC);
                    p1 = g_xr + (size_t)(row0 + 8) * HC + (col - HC);
                }
                if (row0 < M) {
                    float2 o = make_float2(acc[mi][ni][0] + b0, acc[mi][ni][1] + b1);
                    *(float2*)p0 = o;
                }
                if (row0 + 8 < M) {
                    float2 o = make_float2(acc[mi][ni][2] + b0, acc[mi][ni][3] + b1);
                    *(float2*)p1 = o;
                }
            }
        }
    }
}

// ---------------- fused online-softmax node kernel ----------------
// 384 threads/block (one node); thread owns 8 contiguous channels of ONE head
// (warps 0-3 -> head0, 4-7 -> head1, 8-11 -> head2). One v8 gather per thread
// per edge; xl kept L2-resident (evict_last), xr streamed (evict_first).
__global__ __launch_bounds__(384) void k_node(const float* __restrict__ att,
                                              const float* __restrict__ bias)
{
    __shared__ int   ssrc[SMAX];
    __shared__ float wred[2][12];
    __shared__ __align__(16) float scomb[HC];

    const int n    = blockIdx.x;
    const int tid  = threadIdx.x;
    const int lane = tid & 31, warp = tid >> 5;
    const int head = warp >> 2;               // 0..2
    const int s    = g_off[n];
    const int deg  = g_off[n + 1] - s;
    const bool insm = (deg <= SMAX);

    // own 8 channels of xr[n] (read-once: evict_first) and att (plain)
    float r[8], a[8];
    ld8_ef(g_xr + (size_t)n * HC + tid * 8, r);
    {
        const float4* ap = (const float4*)(att + tid * 8);
        float4 q0 = ap[0], q1 = ap[1];
        a[0]=q0.x; a[1]=q0.y; a[2]=q0.z; a[3]=q0.w;
        a[4]=q1.x; a[5]=q1.y; a[6]=q1.z; a[7]=q1.w;
    }

    for (int i = tid; i < deg && i < SMAX; i += 384) ssrc[i] = g_csrc[s + i];
    __syncthreads();
    // deterministic order: sort srcs ascending (deg ~11)
    if (tid == 0 && insm && deg > 1) {
        for (int i = 1; i < deg; i++) {
            int v = ssrc[i]; int j = i - 1;
            while (j >= 0 && ssrc[j] > v) { ssrc[j + 1] = ssrc[j]; j--; }
            ssrc[j + 1] = v;
        }
    }
    __syncthreads();

    float m = -1e30f, d = 0.f;
    float A[8] = {0.f,0.f,0.f,0.f,0.f,0.f,0.f,0.f};

    // prefetch edge 0 (reused set: evict_last)
    int j0 = insm ? ssrc[0] : g_csrc[s];
    float v[8];
    ld8_el(g_xl + (size_t)j0 * HC + tid * 8, v);

    for (int i = 0; i < deg; i++) {
        float c[8];
#pragma unroll
        for (int k = 0; k < 8; k++) c[k] = v[k];
        if (i + 1 < deg) {
            int j2 = insm ? ssrc[i + 1] : g_csrc[s + i + 1];
            ld8_el(g_xl + (size_t)j2 * HC + tid * 8, v);
        }
        // own-head partial score over 8 channels
        float pp = 0.f;
#pragma unroll
        for (int k = 0; k < 8; k++) {
            float t = c[k] + r[k];
            t = t > 0.f ? t : NEG * t;
            pp += t * a[k];
        }
#pragma unroll
        for (int o = 16; o; o >>= 1) pp += __shfl_xor_sync(0xffffffffu, pp, o);
        float* wb = wred[i & 1];
        if (lane == 0) wb[warp] = pp;
        __syncthreads();
        float sc = wb[head * 4] + wb[head * 4 + 1] + wb[head * 4 + 2] + wb[head * 4 + 3];

        // online softmax update (per own head)
        float mn = fmaxf(m, sc);
        float scale = __expf(m - mn);
        float e = __expf(sc - mn);
        d = d * scale + e; m = mn;
#pragma unroll
        for (int k = 0; k < 8; k++) A[k] = A[k] * scale + e * c[k];
    }

    // normalize own head, include 1/3 head-mean factor; combine via SMEM
    float inv = (1.f / (d + 1e-16f)) * (1.f / 3.f);
#pragma unroll
    for (int k = 0; k < 8; k++) scomb[tid * 8 + k] = A[k] * inv;
    __syncthreads();
    if (tid < 256) {
        float4 s0 = ((const float4*)scomb)[tid];        // head0, channels 4t..
        float4 s1 = ((const float4*)scomb)[tid + 256];  // head1
        float4 s2 = ((const float4*)scomb)[tid + 512];  // head2
        float4 bb = ((const float4*)bias)[tid];
        float4 o;
        o.x = ftf32(s0.x + s1.x + s2.x + bb.x);
        o.y = ftf32(s0.y + s1.y + s2.y + bb.y);
        o.z = ftf32(s0.z + s1.z + s2.z + bb.z);
        o.w = ftf32(s0.w + s1.w + s2.w + bb.w);
        ((float4*)(g_hpre + (size_t)n * KDIM))[tid] = o;
    }
}

// ---------------- launch ----------------
extern "C" void kernel_launch(void* const* d_in, const int* in_sizes, int n_in,
                              void* d_out, int out_size) {
    (void)n_in;
    const float*     x      = (const float*)d_in[0];
    const long long* e64    = (const long long*)d_in[1];
    const int*       e32    = (const int*)d_in[1];
    const float*     Wl     = (const float*)d_in[2];
    const float*     bl     = (const float*)d_in[3];
    const float*     Wr     = (const float*)d_in[4];
    const float*     br     = (const float*)d_in[5];
    const float*     att    = (const float*)d_in[6];
    const float*     bias   = (const float*)d_in[7];
    const float*     Wfc    = (const float*)d_in[8];
    const float*     bfc    = (const float*)d_in[9];
    const float*     exps   = (const float*)d_in[10];
    const float*     exps_c = (const float*)d_in[11];
    float* out = (float*)d_out;

    cudaFuncSetAttribute(k_gemm, cudaFuncAttributeMaxDynamicSharedMemorySize, 65536);

    // cvt + projection GEMM first (independent of CSR; also puts k_gemm in the
    // ncu-profiled launch slot for real roofline evidence)
    k_cvtX<<<(NNODES * KDIM / 4 + 255) / 256, 256>>>(x);
    k_cvtW<<<(KDIM * HC2 / 4 + 255) / 256, 256>>>(Wl, Wr);
    k_cvtF<<<(KDIM * NCLS / 4 + 255) / 256, 256>>>(Wfc);
    {
        dim3 grid(HC2 / 128, (NNODES + 127) / 128);
        k_gemm<<<grid, 256, 65536>>>(0, NNODES, HC2, HC, bl, br, nullptr);
    }

    // CSR build (by destination)
    k_detect<<<1, 256>>>(e64);
    k_zero<<<(NNODES + 255) / 256, 256>>>();
    k_deg<<<(ET + 255) / 256, 256>>>(e64, e32);
    k_scan<<<1, 1024>>>();
    k_fill<<<(ET + 255) / 256, 256>>>(e64, e32);

    // fused GATv2 edge phase -> g_hpre (head-mean + conv bias, tf32-rounded)
    k_node<<<NNODES, 384>>>(att, bias);

    // h = g_hpre @ Wfc + bfc -> d_out[0 : N*NC]
    {
        dim3 grid((NCLS + 127) / 128, (NNODES + 127) / 128);
        k_gemm<<<grid, 256, 65536>>>(1, NNODES, NCLS, NCLS, bfc, bfc, out);
    }

    // pass-throughs (guarded by out_size so we can never write past d_out)
    size_t offh = (size_t)NNODES * NCLS;
    size_t nE   = (size_t)in_sizes[10];
    size_t nC   = (size_t)in_sizes[11];
    if ((size_t)out_size >= offh + nE) {
        cudaMemcpyAsync(out + offh, exps, nE * sizeof(float),
                        cudaMemcpyDeviceToDevice, 0);
        if ((size_t)out_size >= offh + nE + nC)
            cudaMemcpyAsync(out + offh + nE, exps_c, nC * sizeof(float),
                            cudaMemcpyDeviceToDevice, 0);
    }
}